// round 8
// baseline (speedup 1.0000x reference)
#include <cuda_runtime.h>
#include <cuda_bf16.h>
#include <math.h>
#include <stdint.h>
#include <stddef.h>

// Problem dims
#define Bz   4
#define Tz   1024
#define Cz   768
#define Hz   12
#define HDz  64
#define BTz  (Bz*Tz)     // 4096
#define BHz  (Bz*Hz)     // 48

// -------- scratch (static device globals; no allocations allowed) --------
__device__ __nv_bfloat16 g_hh  [BTz*Cz];
__device__ __nv_bfloat16 g_hl  [BTz*Cz];
__device__ __nv_bfloat16 g_qkvh[BTz*3*Cz];
__device__ __nv_bfloat16 g_qkvl[BTz*3*Cz];
__device__ __nv_bfloat16 g_tabh[Tz*HDz];
__device__ __nv_bfloat16 g_tabl[Tz*HDz];
__device__ float g_qtab[(size_t)BHz*Tz*Tz];
__device__ __nv_bfloat16 g_yh  [BTz*Cz];
__device__ __nv_bfloat16 g_yl  [BTz*Cz];
__device__ float g_x1  [BTz*Cz];
__device__ __nv_bfloat16 g_h2h [BTz*Cz];
__device__ __nv_bfloat16 g_h2l [BTz*Cz];
__device__ __nv_bfloat16 g_fch [BTz*4*Cz];
__device__ __nv_bfloat16 g_fcl [BTz*4*Cz];

// transposed + bf16-split weights: [N,K] layout, hi and lo parts
#define WT_TOTAL 7077888
#define WT_ATTN  0
#define WT_CPROJ 1769472
#define WT_FC    2359296
#define WT_MPROJ 4718592
__device__ __nv_bfloat16 g_bt_hi[WT_TOTAL];
__device__ __nv_bfloat16 g_bt_lo[WT_TOTAL];

// =========================================================================
// mma.sync m16n8k16 bf16 (row.col), fp32 accum + ldmatrix
// =========================================================================
__device__ __forceinline__ void mma16816(float* c, const uint32_t* a,
                                         const uint32_t* b) {
    asm volatile(
        "mma.sync.aligned.m16n8k16.row.col.f32.bf16.bf16.f32 "
        "{%0,%1,%2,%3}, {%4,%5,%6,%7}, {%8,%9}, {%0,%1,%2,%3};"
        : "+f"(c[0]), "+f"(c[1]), "+f"(c[2]), "+f"(c[3])
        : "r"(a[0]), "r"(a[1]), "r"(a[2]), "r"(a[3]), "r"(b[0]), "r"(b[1]));
}
__device__ __forceinline__ void ldsm4(uint32_t* r, uint32_t addr) {
    asm volatile(
        "ldmatrix.sync.aligned.m8n8.x4.shared.b16 {%0,%1,%2,%3}, [%4];"
        : "=r"(r[0]), "=r"(r[1]), "=r"(r[2]), "=r"(r[3]) : "r"(addr));
}

// cp.async helpers
__device__ __forceinline__ void cpa16(uint32_t dst, const void* src) {
    asm volatile("cp.async.cg.shared.global [%0], [%1], 16;" :: "r"(dst),
                 "l"(src));
}
#define CP_COMMIT() asm volatile("cp.async.commit_group;" ::: "memory")
#define CP_WAIT1()  asm volatile("cp.async.wait_group 1;" ::: "memory")
#define CP_WAIT0()  asm volatile("cp.async.wait_group 0;" ::: "memory")

// fast exp2 on the FMA pipe
__device__ __forceinline__ float fexp2(float t) {
    t = fmaxf(t, -80.f);
    int i = __float2int_rn(t);
    float r = t - (float)i;
    float q = 1.5403530e-4f;
    q = fmaf(q, r, 1.3333558e-3f);
    q = fmaf(q, r, 9.6181291e-3f);
    q = fmaf(q, r, 5.5504109e-2f);
    q = fmaf(q, r, 2.4022651e-1f);
    q = fmaf(q, r, 6.9314718e-1f);
    q = fmaf(q, r, 1.0f);
    return q * __int_as_float((i + 127) << 23);
}
#define CEXP 0.18033688011112042f

__device__ __forceinline__ void split2(float x, float y, uint32_t& h,
                                       uint32_t& l) {
    __nv_bfloat162 hh = __floats2bfloat162_rn(x, y);
    __nv_bfloat162 ll = __floats2bfloat162_rn(x - __bfloat162float(hh.x),
                                              y - __bfloat162float(hh.y));
    h = *(uint32_t*)&hh;
    l = *(uint32_t*)&ll;
}

// =========================================================================
// weight transpose + bf16 hi/lo split: src[K,N] -> dst_hi/lo[N,K]
// =========================================================================
__global__ __launch_bounds__(256)
void k_tsplit(const float* __restrict__ src, __nv_bfloat16* __restrict__ hi,
              __nv_bfloat16* __restrict__ lo, int K, int N) {
    __shared__ float t[32][33];
    int k0 = blockIdx.x * 32, n0 = blockIdx.y * 32;
    int tx = threadIdx.x & 31, ty = threadIdx.x >> 5;
#pragma unroll
    for (int r = 0; r < 32; r += 8)
        t[ty + r][tx] = src[(size_t)(k0 + ty + r) * N + n0 + tx];
    __syncthreads();
#pragma unroll
    for (int r = 0; r < 32; r += 8) {
        float v = t[tx][ty + r];
        __nv_bfloat16 h = __float2bfloat16(v);
        size_t o = (size_t)(n0 + ty + r) * K + k0 + tx;
        hi[o] = h;
        lo[o] = __float2bfloat16(v - __bfloat162float(h));
    }
}

// =========================================================================
// bf16x3 tensor-core GEMM, cp.async + ldmatrix, 4 warps x (64x64) tiles.
// A as bf16 hi/lo [M,K]; W as Bt[N,K] bf16 hi/lo.
// EPI: 1 +Cin (fp32 out), 3 bf16 hi/lo out, 4 GELU -> bf16 hi/lo out
// =========================================================================
#define PITCH 40
#define ROW_B  80                      // bytes per smem row
#define ARR_B  10240                   // 128*80
#define STG_B  (4 * ARR_B)
#define SMEM_MMA (2 * STG_B)           // 81920

template <int EPI>
__global__ __launch_bounds__(128, 2)
void k_mma2(const __nv_bfloat16* __restrict__ Agh,
            const __nv_bfloat16* __restrict__ Agl,
            const __nv_bfloat16* __restrict__ Bth,
            const __nv_bfloat16* __restrict__ Btl,
            const float* __restrict__ Cin, float* __restrict__ D,
            __nv_bfloat16* __restrict__ Dh, __nv_bfloat16* __restrict__ Dl,
            int M, int N, int K) {
    extern __shared__ __nv_bfloat16 smp[];
    const int tid = threadIdx.x;
    const int wid = tid >> 5, lane = tid & 31;
    const int wm = wid & 1, wn = wid >> 1;     // 2x2 warp grid, 64x64 tiles
    const int m0 = blockIdx.y << 7, n0 = blockIdx.x << 7;
    const int gq = lane >> 2, kq = (lane & 3) << 1;

    uint32_t sbase;
    asm("{ .reg .u64 t; cvta.to.shared.u64 t, %1; cvt.u32.u64 %0, t; }"
        : "=r"(sbase) : "l"(smp));

    // loader: thread tid owns row tid of all four arrays
    const __nv_bfloat16* gAh = Agh + (size_t)(m0 + tid) * K;
    const __nv_bfloat16* gAl = Agl + (size_t)(m0 + tid) * K;
    const __nv_bfloat16* gBh = Bth + (size_t)(n0 + tid) * K;
    const __nv_bfloat16* gBl = Btl + (size_t)(n0 + tid) * K;
    const uint32_t drow = (uint32_t)tid * ROW_B;

    // ldmatrix lane-address offsets (bytes within an array)
    const uint32_t aOff =
        (uint32_t)(wm * 64 + (lane & 15)) * ROW_B + ((lane >> 4) << 4);
    const uint32_t bOff =
        (uint32_t)(wn * 64 + (lane & 7) + ((lane >> 4) << 3)) * ROW_B +
        (((lane >> 3) & 1) << 4);

    float acc[4][8][4];
#pragma unroll
    for (int mi = 0; mi < 4; mi++)
#pragma unroll
        for (int ni = 0; ni < 8; ni++)
#pragma unroll
            for (int j = 0; j < 4; j++) acc[mi][ni][j] = 0.f;

    const int nc = K >> 5;
    // prefetch chunk 0
    {
        uint32_t sb = sbase + drow;
#pragma unroll
        for (int q = 0; q < 4; q++) {
            cpa16(sb + q * 16, (const char*)gAh + q * 16);
            cpa16(sb + ARR_B + q * 16, (const char*)gAl + q * 16);
            cpa16(sb + 2 * ARR_B + q * 16, (const char*)gBh + q * 16);
            cpa16(sb + 3 * ARR_B + q * 16, (const char*)gBl + q * 16);
        }
        CP_COMMIT();
    }

    for (int c = 0; c < nc; c++) {
        if (c + 1 < nc) {
            uint32_t sb = sbase + ((c + 1) & 1) * STG_B + drow;
            const char* pAh = (const char*)(gAh + ((c + 1) << 5));
            const char* pAl = (const char*)(gAl + ((c + 1) << 5));
            const char* pBh = (const char*)(gBh + ((c + 1) << 5));
            const char* pBl = (const char*)(gBl + ((c + 1) << 5));
#pragma unroll
            for (int q = 0; q < 4; q++) {
                cpa16(sb + q * 16, pAh + q * 16);
                cpa16(sb + ARR_B + q * 16, pAl + q * 16);
                cpa16(sb + 2 * ARR_B + q * 16, pBh + q * 16);
                cpa16(sb + 3 * ARR_B + q * 16, pBl + q * 16);
            }
            CP_COMMIT();
            CP_WAIT1();
        } else {
            CP_WAIT0();
        }
        __syncthreads();
        const uint32_t stg = sbase + (c & 1) * STG_B;
        const uint32_t pAh = stg, pAl = stg + ARR_B;
        const uint32_t pBh = stg + 2 * ARR_B, pBl = stg + 3 * ARR_B;

#pragma unroll
        for (int ko = 0; ko < 2; ko++) {   // k halves: byte offset ko*32
            const uint32_t kb = ko << 5;
            uint32_t Bh[4][4], Bl[4][4];
#pragma unroll
            for (int nip = 0; nip < 4; nip++) {
                uint32_t bo = bOff + nip * (16 * ROW_B) + kb;
                ldsm4(Bh[nip], pBh + bo);
                ldsm4(Bl[nip], pBl + bo);
            }
#pragma unroll
            for (int mi = 0; mi < 4; mi++) {
                uint32_t ao = aOff + mi * (16 * ROW_B) + kb;
                uint32_t Ah[4], Al[4];
                ldsm4(Ah, pAh + ao);
                ldsm4(Al, pAl + ao);
#pragma unroll
                for (int ni = 0; ni < 8; ni++) {
                    const uint32_t* bh = &Bh[ni >> 1][(ni & 1) * 2];
                    const uint32_t* bl = &Bl[ni >> 1][(ni & 1) * 2];
                    mma16816(acc[mi][ni], Ah, bh);
                    mma16816(acc[mi][ni], Ah, bl);
                    mma16816(acc[mi][ni], Al, bh);
                }
            }
        }
        __syncthreads();
    }

#pragma unroll
    for (int mi = 0; mi < 4; mi++) {
#pragma unroll
        for (int ni = 0; ni < 8; ni++) {
#pragma unroll
            for (int half = 0; half < 2; half++) {
                int r = m0 + wm * 64 + mi * 16 + gq + half * 8;
                int cc = n0 + wn * 64 + ni * 8 + kq;
                size_t o = (size_t)r * N + cc;
                float vx = acc[mi][ni][half * 2 + 0];
                float vy = acc[mi][ni][half * 2 + 1];
                if (EPI == 1) {
                    float2 ci = *(const float2*)(Cin + o);
                    *(float2*)(D + o) = make_float2(vx + ci.x, vy + ci.y);
                }
                if (EPI == 4) {
                    vx = 0.5f * vx * (1.f + erff(vx * 0.70710678118654752f));
                    vy = 0.5f * vy * (1.f + erff(vy * 0.70710678118654752f));
                }
                if (EPI == 3 || EPI == 4) {
                    uint32_t h, l;
                    split2(vx, vy, h, l);
                    *(uint32_t*)&Dh[o] = h;
                    *(uint32_t*)&Dl[o] = l;
                }
            }
        }
    }
}

// =========================================================================
// Sinusoidal table -> bf16 hi/lo
// =========================================================================
__global__ void k_tab(__nv_bfloat16* __restrict__ th,
                      __nv_bfloat16* __restrict__ tl) {
    int idx = blockIdx.x * blockDim.x + threadIdx.x;
    if (idx >= Tz * HDz) return;
    int delta = idx / HDz, d = idx % HDz;
    int j = (d < 32) ? d : d - 32;
    float inv = expf(-logf(10000.f) * (2.f * (float)j) / 64.f);
    float a = (float)delta * inv;
    float v = (d < 32) ? sinf(a) : cosf(a);
    __nv_bfloat16 h = __float2bfloat16(v);
    th[idx] = h;
    tl[idx] = __float2bfloat16(v - __bfloat162float(h));
}

// =========================================================================
// LayerNorm -> bf16 hi/lo
// =========================================================================
__global__ __launch_bounds__(256)
void k_ln(const float* __restrict__ x, const float* __restrict__ w,
          __nv_bfloat16* __restrict__ oh, __nv_bfloat16* __restrict__ ol) {
    __shared__ float red[256];
    int row = blockIdx.x;
    int tid = threadIdx.x;
    const float* xr = x + (size_t)row * Cz;
    float v0 = xr[tid], v1 = xr[tid + 256], v2 = xr[tid + 512];
    red[tid] = v0 + v1 + v2;
    __syncthreads();
    for (int o = 128; o > 0; o >>= 1) {
        if (tid < o) red[tid] += red[tid + o];
        __syncthreads();
    }
    float mean = red[0] * (1.f / Cz);
    __syncthreads();
    float d0 = v0 - mean, d1 = v1 - mean, d2 = v2 - mean;
    red[tid] = d0 * d0 + d1 * d1 + d2 * d2;
    __syncthreads();
    for (int o = 128; o > 0; o >>= 1) {
        if (tid < o) red[tid] += red[tid + o];
        __syncthreads();
    }
    float rstd = rsqrtf(red[0] * (1.f / Cz) + 1e-5f);
    size_t base = (size_t)row * Cz;
#pragma unroll
    for (int s = 0; s < 3; s++) {
        int cc = tid + s * 256;
        float v = ((s == 0) ? d0 : (s == 1) ? d1 : d2) * rstd * w[cc];
        __nv_bfloat16 h = __float2bfloat16(v);
        oh[base + cc] = h;
        ol[base + cc] = __float2bfloat16(v - __bfloat162float(h));
    }
}

// =========================================================================
// qtab via mma (dt<=it only)
// =========================================================================
#define AP 72

__global__ __launch_bounds__(128)
void k_qtabm(const __nv_bfloat16* __restrict__ qkvh,
             const __nv_bfloat16* __restrict__ qkvl,
             const __nv_bfloat16* __restrict__ tabh,
             const __nv_bfloat16* __restrict__ tabl,
             float* __restrict__ qtab) {
    int bh = blockIdx.x;
    int it = gridDim.y - 1 - blockIdx.y;
    int dt = blockIdx.z;
    if (dt > it) return;
    int b = bh / Hz, h = bh % Hz;

    __shared__ __nv_bfloat16 sQh[64 * AP], sQl[64 * AP];
    __shared__ __nv_bfloat16 sTh[64 * AP], sTl[64 * AP];

    int tid = threadIdx.x;
    int wid = tid >> 5, lane = tid & 31;
    int gq = lane >> 2, kq = (lane & 3) << 1;

    {
        int r = tid >> 1, cb = (tid & 1) << 5;
        const __nv_bfloat16* qh =
            qkvh + (size_t)(b * Tz + it * 64 + r) * (3 * Cz) + h * HDz + cb;
        const __nv_bfloat16* ql =
            qkvl + (size_t)(b * Tz + it * 64 + r) * (3 * Cz) + h * HDz + cb;
#pragma unroll
        for (int j = 0; j < 32; j += 8) {
            *(uint4*)&sQh[r * AP + cb + j] = *(const uint4*)(qh + j);
            *(uint4*)&sQl[r * AP + cb + j] = *(const uint4*)(ql + j);
        }
        const __nv_bfloat16* th = tabh + (size_t)(dt * 64 + r) * HDz + cb;
        const __nv_bfloat16* tl = tabl + (size_t)(dt * 64 + r) * HDz + cb;
#pragma unroll
        for (int j = 0; j < 32; j += 8) {
            *(uint4*)&sTh[r * AP + cb + j] = *(const uint4*)(th + j);
            *(uint4*)&sTl[r * AP + cb + j] = *(const uint4*)(tl + j);
        }
    }
    __syncthreads();

    float S[8][4];
#pragma unroll
    for (int ni = 0; ni < 8; ni++)
#pragma unroll
        for (int j = 0; j < 4; j++) S[ni][j] = 0.f;

#pragma unroll
    for (int kt = 0; kt < 4; kt++) {
        int r0 = wid * 16 + gq, ko = kt * 16;
        uint32_t ah[4], al[4];
        ah[0] = *(const uint32_t*)&sQh[r0 * AP + ko + kq];
        ah[1] = *(const uint32_t*)&sQh[(r0 + 8) * AP + ko + kq];
        ah[2] = *(const uint32_t*)&sQh[r0 * AP + ko + kq + 8];
        ah[3] = *(const uint32_t*)&sQh[(r0 + 8) * AP + ko + kq + 8];
        al[0] = *(const uint32_t*)&sQl[r0 * AP + ko + kq];
        al[1] = *(const uint32_t*)&sQl[(r0 + 8) * AP + ko + kq];
        al[2] = *(const uint32_t*)&sQl[r0 * AP + ko + kq + 8];
        al[3] = *(const uint32_t*)&sQl[(r0 + 8) * AP + ko + kq + 8];
#pragma unroll
        for (int ni = 0; ni < 8; ni++) {
            int row = ni * 8 + gq;
            uint32_t bh2[2], bl2[2];
            bh2[0] = *(const uint32_t*)&sTh[row * AP + ko + kq];
            bh2[1] = *(const uint32_t*)&sTh[row * AP + ko + kq + 8];
            bl2[0] = *(const uint32_t*)&sTl[row * AP + ko + kq];
            bl2[1] = *(const uint32_t*)&sTl[row * AP + ko + kq + 8];
            mma16816(S[ni], ah, bh2);
            mma16816(S[ni], ah, bl2);
            mma16816(S[ni], al, bh2);
        }
    }

    int ia = it * 64 + wid * 16 + gq;
#pragma unroll
    for (int ni = 0; ni < 8; ni++) {
        int col = dt * 64 + ni * 8 + kq;
        size_t oa = ((size_t)bh * Tz + ia) * Tz + col;
        *(float2*)&qtab[oa] = make_float2(S[ni][0], S[ni][1]);
        size_t ob = ((size_t)bh * Tz + ia + 8) * Tz + col;
        *(float2*)&qtab[ob] = make_float2(S[ni][2], S[ni][3]);
    }
}

// =========================================================================
// Tensor-core fused causal attention (outputs bf16 hi/lo)
// =========================================================================
__global__ __launch_bounds__(128)
void k_attnm(const __nv_bfloat16* __restrict__ qkvh,
             const __nv_bfloat16* __restrict__ qkvl,
             const float* __restrict__ qtab,
             __nv_bfloat16* __restrict__ yh, __nv_bfloat16* __restrict__ yl) {
    __shared__ __nv_bfloat16 sQh[64 * AP], sQl[64 * AP];
    __shared__ __nv_bfloat16 sKh[64 * AP], sKl[64 * AP];

    int bh = blockIdx.x;
    int it = gridDim.y - 1 - blockIdx.y;
    int b = bh / Hz, h = bh % Hz;
    int i0 = it * 64;
    int tid = threadIdx.x;
    int wid = tid >> 5, lane = tid & 31;
    int gq = lane >> 2, kq = (lane & 3) << 1;

    {
        int r = tid >> 1, cb = (tid & 1) << 5;
        const __nv_bfloat16* qh =
            qkvh + (size_t)(b * Tz + i0 + r) * (3 * Cz) + h * HDz + cb;
        const __nv_bfloat16* ql =
            qkvl + (size_t)(b * Tz + i0 + r) * (3 * Cz) + h * HDz + cb;
#pragma unroll
        for (int j = 0; j < 32; j += 8) {
            *(uint4*)&sQh[r * AP + cb + j] = *(const uint4*)(qh + j);
            *(uint4*)&sQl[r * AP + cb + j] = *(const uint4*)(ql + j);
        }
    }
    __syncthreads();

    uint32_t aQh[4][4], aQl[4][4];
#pragma unroll
    for (int kt = 0; kt < 4; kt++) {
        int r0 = wid * 16 + gq, ko = kt * 16;
        aQh[kt][0] = *(const uint32_t*)&sQh[r0 * AP + ko + kq];
        aQh[kt][1] = *(const uint32_t*)&sQh[(r0 + 8) * AP + ko + kq];
        aQh[kt][2] = *(const uint32_t*)&sQh[r0 * AP + ko + kq + 8];
        aQh[kt][3] = *(const uint32_t*)&sQh[(r0 + 8) * AP + ko + kq + 8];
        aQl[kt][0] = *(const uint32_t*)&sQl[r0 * AP + ko + kq];
        aQl[kt][1] = *(const uint32_t*)&sQl[(r0 + 8) * AP + ko + kq];
        aQl[kt][2] = *(const uint32_t*)&sQl[r0 * AP + ko + kq + 8];
        aQl[kt][3] = *(const uint32_t*)&sQl[(r0 + 8) * AP + ko + kq + 8];
    }

    float O[8][4];
#pragma unroll
    for (int ni = 0; ni < 8; ni++)
#pragma unroll
        for (int j = 0; j < 4; j++) O[ni][j] = 0.f;
    float m_a = -1e30f, m_b = -1e30f, l_a = 0.f, l_b = 0.f;

    const float* qt0 = qtab + (size_t)bh * Tz * Tz;
    const int ia = i0 + wid * 16 + gq;
    const int ib = ia + 8;

    for (int jt = 0; jt <= it; jt++) {
        int j0 = jt * 64;
        __syncthreads();
        {
            int r = tid >> 1, cb = (tid & 1) << 5;
            const __nv_bfloat16* kh =
                qkvh + (size_t)(b * Tz + j0 + r) * (3 * Cz) + Cz + h * HDz + cb;
            const __nv_bfloat16* kl =
                qkvl + (size_t)(b * Tz + j0 + r) * (3 * Cz) + Cz + h * HDz + cb;
#pragma unroll
            for (int j = 0; j < 32; j += 8) {
                *(uint4*)&sKh[r * AP + cb + j] = *(const uint4*)(kh + j);
                *(uint4*)&sKl[r * AP + cb + j] = *(const uint4*)(kl + j);
            }
        }
        __syncthreads();

        float S[8][4];
#pragma unroll
        for (int ni = 0; ni < 8; ni++)
#pragma unroll
            for (int j = 0; j < 4; j++) S[ni][j] = 0.f;
#pragma unroll
        for (int kt = 0; kt < 4; kt++) {
            int ko = kt * 16;
#pragma unroll
            for (int ni = 0; ni < 8; ni++) {
                int row = ni * 8 + gq;
                uint32_t bh2[2], bl2[2];
                bh2[0] = *(const uint32_t*)&sKh[row * AP + ko + kq];
                bh2[1] = *(const uint32_t*)&sKh[row * AP + ko + kq + 8];
                bl2[0] = *(const uint32_t*)&sKl[row * AP + ko + kq];
                bl2[1] = *(const uint32_t*)&sKl[row * AP + ko + kq + 8];
                mma16816(S[ni], aQh[kt], bh2);
                mma16816(S[ni], aQh[kt], bl2);
                mma16816(S[ni], aQl[kt], bh2);
            }
        }

        bool diag = (jt == it);
#pragma unroll
        for (int ni = 0; ni < 8; ni++) {
            int jbase = j0 + ni * 8 + kq;
#pragma unroll
            for (int c = 0; c < 4; c++) {
                int row = (c < 2) ? ia : ib;
                int j = jbase + (c & 1);
                if (diag && j > row)
                    S[ni][c] = -1e30f;
                else
                    S[ni][c] += qt0[(size_t)row * Tz + (row - j)];
            }
        }

        float mt_a = -1e30f, mt_b = -1e30f;
#pragma unroll
        for (int ni = 0; ni < 8; ni++) {
            mt_a = fmaxf(mt_a, fmaxf(S[ni][0], S[ni][1]));
            mt_b = fmaxf(mt_b, fmaxf(S[ni][2], S[ni][3]));
        }
        mt_a = fmaxf(mt_a, __shfl_xor_sync(0xffffffffu, mt_a, 1));
        mt_a = fmaxf(mt_a, __shfl_xor_sync(0xffffffffu, mt_a, 2));
        mt_b = fmaxf(mt_b, __shfl_xor_sync(0xffffffffu, mt_b, 1));
        mt_b = fmaxf(mt_b, __shfl_xor_sync(0xffffffffu, mt_b, 2));
        float mn_a = fmaxf(m_a, mt_a), mn_b = fmaxf(m_b, mt_b);
        float al_a = fexp2((m_a - mn_a) * CEXP);
        float al_b = fexp2((m_b - mn_b) * CEXP);
        m_a = mn_a;
        m_b = mn_b;
        float sum_a = 0.f, sum_b = 0.f;
#pragma unroll
        for (int ni = 0; ni < 8; ni++) {
            float p0 = fexp2((S[ni][0] - mn_a) * CEXP);
            float p1 = fexp2((S[ni][1] - mn_a) * CEXP);
            float p2 = fexp2((S[ni][2] - mn_b) * CEXP);
            float p3 = fexp2((S[ni][3] - mn_b) * CEXP);
            S[ni][0] = p0; S[ni][1] = p1; S[ni][2] = p2; S[ni][3] = p3;
            sum_a += p0 + p1;
            sum_b += p2 + p3;
        }
        sum_a += __shfl_xor_sync(0xffffffffu, sum_a, 1);
        sum_a += __shfl_xor_sync(0xffffffffu, sum_a, 2);
        sum_b += __shfl_xor_sync(0xffffffffu, sum_b, 1);
        sum_b += __shfl_xor_sync(0xffffffffu, sum_b, 2);
        l_a = l_a * al_a + sum_a;
        l_b = l_b * al_b + sum_b;
#pragma unroll
        for (int ni = 0; ni < 8; ni++) {
            O[ni][0] *= al_a;
            O[ni][1] *= al_a;
            O[ni][2] *= al_b;
            O[ni][3] *= al_b;
        }

        __syncthreads();
        {
            const size_t vbase =
                (size_t)(b * Tz + j0) * (3 * Cz) + 2 * Cz + h * HDz;
#pragma unroll
            for (int n = 0; n < 8; n++) {
                int u = n * 128 + tid;
                int j = (u >> 5) << 1;
                int d = (u & 31) << 1;
                const __nv_bfloat16* sh = qkvh + vbase + (size_t)j * (3 * Cz) + d;
                uint32_t va = *(const uint32_t*)sh;
                uint32_t vb = *(const uint32_t*)(sh + 3 * Cz);
                *(uint32_t*)&sKh[d * AP + j] = __byte_perm(va, vb, 0x5410);
                *(uint32_t*)&sKh[(d + 1) * AP + j] = __byte_perm(va, vb, 0x7632);
                const __nv_bfloat16* sl = qkvl + vbase + (size_t)j * (3 * Cz) + d;
                va = *(const uint32_t*)sl;
                vb = *(const uint32_t*)(sl + 3 * Cz);
                *(uint32_t*)&sKl[d * AP + j] = __byte_perm(va, vb, 0x5410);
                *(uint32_t*)&sKl[(d + 1) * AP + j] = __byte_perm(va, vb, 0x7632);
            }
        }
        __syncthreads();

#pragma unroll
        for (int kt = 0; kt < 4; kt++) {
            int ko = kt * 16;
            uint32_t aPh[4], aPl[4];
            split2(S[2 * kt][0], S[2 * kt][1], aPh[0], aPl[0]);
            split2(S[2 * kt][2], S[2 * kt][3], aPh[1], aPl[1]);
            split2(S[2 * kt + 1][0], S[2 * kt + 1][1], aPh[2], aPl[2]);
            split2(S[2 * kt + 1][2], S[2 * kt + 1][3], aPh[3], aPl[3]);
#pragma unroll
            for (int nd = 0; nd < 8; nd++) {
                int row = nd * 8 + gq;
                uint32_t bh2[2], bl2[2];
                bh2[0] = *(const uint32_t*)&sKh[row * AP + ko + kq];
                bh2[1] = *(const uint32_t*)&sKh[row * AP + ko + kq + 8];
                bl2[0] = *(const uint32_t*)&sKl[row * AP + ko + kq];
                bl2[1] = *(const uint32_t*)&sKl[row * AP + ko + kq + 8];
                mma16816(O[nd], aPh, bh2);
                mma16816(O[nd], aPh, bl2);
                mma16816(O[nd], aPl, bh2);
            }
        }
    }

    float inv_a = 1.f / l_a, inv_b = 1.f / l_b;
#pragma unroll
    for (int nd = 0; nd < 8; nd++) {
        int col = h * HDz + nd * 8 + kq;
        uint32_t h32, l32;
        split2(O[nd][0] * inv_a, O[nd][1] * inv_a, h32, l32);
        size_t oa = (size_t)(b * Tz + ia) * Cz + col;
        *(uint32_t*)&yh[oa] = h32;
        *(uint32_t*)&yl[oa] = l32;
        split2(O[nd][2] * inv_b, O[nd][3] * inv_b, h32, l32);
        size_t ob = (size_t)(b * Tz + ib) * Cz + col;
        *(uint32_t*)&yh[ob] = h32;
        *(uint32_t*)&yl[ob] = l32;
    }
}

// =========================================================================
// launcher
// =========================================================================
extern "C" void kernel_launch(void* const* d_in, const int* in_sizes, int n_in,
                              void* d_out, int out_size) {
    const float* x       = (const float*)d_in[0];
    const float* ln1_w   = (const float*)d_in[1];
    const float* w_attn  = (const float*)d_in[2];
    // d_in[3] = w_pos : dead code in the reference
    const float* w_cproj = (const float*)d_in[4];
    const float* ln2_w   = (const float*)d_in[5];
    const float* w_fc    = (const float*)d_in[6];
    const float* w_mproj = (const float*)d_in[7];
    float* out = (float*)d_out;

    float *qtab, *x1;
    __nv_bfloat16 *bth, *btl, *qkvh, *qkvl, *tabh, *tabl;
    __nv_bfloat16 *hh, *hl, *yh, *yl, *h2h, *h2l, *fch, *fcl;
    cudaGetSymbolAddress((void**)&hh, g_hh);
    cudaGetSymbolAddress((void**)&hl, g_hl);
    cudaGetSymbolAddress((void**)&qkvh, g_qkvh);
    cudaGetSymbolAddress((void**)&qkvl, g_qkvl);
    cudaGetSymbolAddress((void**)&tabh, g_tabh);
    cudaGetSymbolAddress((void**)&tabl, g_tabl);
    cudaGetSymbolAddress((void**)&qtab, g_qtab);
    cudaGetSymbolAddress((void**)&yh, g_yh);
    cudaGetSymbolAddress((void**)&yl, g_yl);
    cudaGetSymbolAddress((void**)&x1, g_x1);
    cudaGetSymbolAddress((void**)&h2h, g_h2h);
    cudaGetSymbolAddress((void**)&h2l, g_h2l);
    cudaGetSymbolAddress((void**)&fch, g_fch);
    cudaGetSymbolAddress((void**)&fcl, g_fcl);
    cudaGetSymbolAddress((void**)&bth, g_bt_hi);
    cudaGetSymbolAddress((void**)&btl, g_bt_lo);

    cudaFuncSetAttribute(k_mma2<1>, cudaFuncAttributeMaxDynamicSharedMemorySize, SMEM_MMA);
    cudaFuncSetAttribute(k_mma2<3>, cudaFuncAttributeMaxDynamicSharedMemorySize, SMEM_MMA);
    cudaFuncSetAttribute(k_mma2<4>, cudaFuncAttributeMaxDynamicSharedMemorySize, SMEM_MMA);

    // weight preprocessing
    k_tsplit<<<dim3(Cz / 32, (3 * Cz) / 32), 256>>>(w_attn, bth + WT_ATTN, btl + WT_ATTN, Cz, 3 * Cz);
    k_tsplit<<<dim3(Cz / 32, Cz / 32), 256>>>(w_cproj, bth + WT_CPROJ, btl + WT_CPROJ, Cz, Cz);
    k_tsplit<<<dim3(Cz / 32, (4 * Cz) / 32), 256>>>(w_fc, bth + WT_FC, btl + WT_FC, Cz, 4 * Cz);
    k_tsplit<<<dim3((4 * Cz) / 32, Cz / 32), 256>>>(w_mproj, bth + WT_MPROJ, btl + WT_MPROJ, 4 * Cz, Cz);

    k_tab<<<(Tz * HDz + 255) / 256, 256>>>(tabh, tabl);
    k_ln<<<BTz, 256>>>(x, ln1_w, hh, hl);

    // qkv = h @ w_attn -> bf16 hi/lo
    k_mma2<3><<<dim3((3 * Cz) / 128, BTz / 128), 128, SMEM_MMA>>>(
        hh, hl, bth + WT_ATTN, btl + WT_ATTN, nullptr, nullptr, qkvh, qkvl,
        BTz, 3 * Cz, Cz);
    // qtab (tensor core)
    k_qtabm<<<dim3(BHz, 16, 16), 128>>>(qkvh, qkvl, tabh, tabl, qtab);
    // fused attention -> y bf16 hi/lo
    k_attnm<<<dim3(BHz, 16), 128>>>(qkvh, qkvl, qtab, yh, yl);
    // x1 = x + y @ w_cproj
    k_mma2<1><<<dim3(Cz / 128, BTz / 128), 128, SMEM_MMA>>>(
        yh, yl, bth + WT_CPROJ, btl + WT_CPROJ, x, x1, nullptr, nullptr,
        BTz, Cz, Cz);
    // LN2 -> bf16 hi/lo
    k_ln<<<BTz, 256>>>(x1, ln2_w, h2h, h2l);
    // fc = gelu(h2 @ w_fc) -> bf16 hi/lo
    k_mma2<4><<<dim3((4 * Cz) / 128, BTz / 128), 128, SMEM_MMA>>>(
        h2h, h2l, bth + WT_FC, btl + WT_FC, nullptr, nullptr, fch, fcl,
        BTz, 4 * Cz, Cz);
    // out = x1 + fc @ w_mproj
    k_mma2<1><<<dim3(Cz / 128, BTz / 128), 128, SMEM_MMA>>>(
        fch, fcl, bth + WT_MPROJ, btl + WT_MPROJ, x1, out, nullptr, nullptr,
        BTz, Cz, 4 * Cz);
}

// round 9
// speedup vs baseline: 1.1526x; 1.1526x over previous
#include <cuda_runtime.h>
#include <cuda_bf16.h>
#include <math.h>
#include <stdint.h>
#include <stddef.h>

// Problem dims
#define Bz   4
#define Tz   1024
#define Cz   768
#define Hz   12
#define HDz  64
#define BTz  (Bz*Tz)     // 4096
#define BHz  (Bz*Hz)     // 48

// -------- scratch (static device globals; no allocations allowed) --------
__device__ __nv_bfloat16 g_hh  [BTz*Cz];
__device__ __nv_bfloat16 g_hl  [BTz*Cz];
__device__ __nv_bfloat16 g_qkvh[BTz*3*Cz];
__device__ __nv_bfloat16 g_qkvl[BTz*3*Cz];
__device__ __nv_bfloat16 g_tkh [Tz*64];   // K-side table: cos(jf)|sin(jf) hi
__device__ __nv_bfloat16 g_tkl [Tz*64];   // lo
__device__ float         g_scq [Tz*64];   // Q-side fp32: sin(if)|cos(if)
__device__ __nv_bfloat16 g_yh  [BTz*Cz];
__device__ __nv_bfloat16 g_yl  [BTz*Cz];
__device__ float g_x1  [BTz*Cz];
__device__ __nv_bfloat16 g_h2h [BTz*Cz];
__device__ __nv_bfloat16 g_h2l [BTz*Cz];
__device__ __nv_bfloat16 g_fch [BTz*4*Cz];
__device__ __nv_bfloat16 g_fcl [BTz*4*Cz];

// transposed + bf16-split weights: [N,K] layout, hi and lo parts
#define WT_TOTAL 7077888
#define WT_ATTN  0
#define WT_CPROJ 1769472
#define WT_FC    2359296
#define WT_MPROJ 4718592
__device__ __nv_bfloat16 g_bt_hi[WT_TOTAL];
__device__ __nv_bfloat16 g_bt_lo[WT_TOTAL];

// =========================================================================
// mma.sync m16n8k16 bf16 (row.col), fp32 accum
// =========================================================================
__device__ __forceinline__ void mma16816(float* c, const uint32_t* a,
                                         const uint32_t* b) {
    asm volatile(
        "mma.sync.aligned.m16n8k16.row.col.f32.bf16.bf16.f32 "
        "{%0,%1,%2,%3}, {%4,%5,%6,%7}, {%8,%9}, {%0,%1,%2,%3};"
        : "+f"(c[0]), "+f"(c[1]), "+f"(c[2]), "+f"(c[3])
        : "r"(a[0]), "r"(a[1]), "r"(a[2]), "r"(a[3]), "r"(b[0]), "r"(b[1]));
}

// cp.async helpers
__device__ __forceinline__ void cpa16(uint32_t dst, const void* src) {
    asm volatile("cp.async.cg.shared.global [%0], [%1], 16;" :: "r"(dst),
                 "l"(src));
}
#define CP_COMMIT() asm volatile("cp.async.commit_group;" ::: "memory")
#define CP_WAIT1()  asm volatile("cp.async.wait_group 1;" ::: "memory")
#define CP_WAIT0()  asm volatile("cp.async.wait_group 0;" ::: "memory")

// fast exp2 on the FMA pipe
__device__ __forceinline__ float fexp2(float t) {
    t = fmaxf(t, -80.f);
    int i = __float2int_rn(t);
    float r = t - (float)i;
    float q = 1.5403530e-4f;
    q = fmaf(q, r, 1.3333558e-3f);
    q = fmaf(q, r, 9.6181291e-3f);
    q = fmaf(q, r, 5.5504109e-2f);
    q = fmaf(q, r, 2.4022651e-1f);
    q = fmaf(q, r, 6.9314718e-1f);
    q = fmaf(q, r, 1.0f);
    return q * __int_as_float((i + 127) << 23);
}
#define CEXP 0.18033688011112042f

__device__ __forceinline__ void split2(float x, float y, uint32_t& h,
                                       uint32_t& l) {
    __nv_bfloat162 hh = __floats2bfloat162_rn(x, y);
    __nv_bfloat162 ll = __floats2bfloat162_rn(x - __bfloat162float(hh.x),
                                              y - __bfloat162float(hh.y));
    h = *(uint32_t*)&hh;
    l = *(uint32_t*)&ll;
}

// =========================================================================
// weight transpose + bf16 hi/lo split
// =========================================================================
__global__ __launch_bounds__(256)
void k_tsplit(const float* __restrict__ src, __nv_bfloat16* __restrict__ hi,
              __nv_bfloat16* __restrict__ lo, int K, int N) {
    __shared__ float t[32][33];
    int k0 = blockIdx.x * 32, n0 = blockIdx.y * 32;
    int tx = threadIdx.x & 31, ty = threadIdx.x >> 5;
#pragma unroll
    for (int r = 0; r < 32; r += 8)
        t[ty + r][tx] = src[(size_t)(k0 + ty + r) * N + n0 + tx];
    __syncthreads();
#pragma unroll
    for (int r = 0; r < 32; r += 8) {
        float v = t[tx][ty + r];
        __nv_bfloat16 h = __float2bfloat16(v);
        size_t o = (size_t)(n0 + ty + r) * K + k0 + tx;
        hi[o] = h;
        lo[o] = __float2bfloat16(v - __bfloat162float(h));
    }
}

// =========================================================================
// bf16x3 tensor-core GEMM (R7 core: 8 warps, cp.async double-buffered)
// EPI: 1 +Cin (fp32 out), 3 bf16 hi/lo out, 4 GELU -> bf16 hi/lo out
// =========================================================================
#define PITCH 40
#define ARR_B  10240
#define STG_B  (4 * ARR_B)
#define SMEM_MMA (2 * STG_B)

__device__ __forceinline__ void gemm_prefetch(
    uint32_t sbase, int c, uint32_t drow, int K,
    const __nv_bfloat16* gAh, const __nv_bfloat16* gAl,
    const __nv_bfloat16* gBh, const __nv_bfloat16* gBl) {
    uint32_t sb = sbase + (uint32_t)(c & 1) * STG_B + drow;
    int k0 = c << 5;
    cpa16(sb,                gAh + k0);
    cpa16(sb + 16,           gAh + k0 + 8);
    cpa16(sb + ARR_B,        gAl + k0);
    cpa16(sb + ARR_B + 16,   gAl + k0 + 8);
    cpa16(sb + 2*ARR_B,      gBh + k0);
    cpa16(sb + 2*ARR_B + 16, gBh + k0 + 8);
    cpa16(sb + 3*ARR_B,      gBl + k0);
    cpa16(sb + 3*ARR_B + 16, gBl + k0 + 8);
}

template <int EPI>
__global__ __launch_bounds__(256, 2)
void k_mma2(const __nv_bfloat16* __restrict__ Agh,
            const __nv_bfloat16* __restrict__ Agl,
            const __nv_bfloat16* __restrict__ Bth,
            const __nv_bfloat16* __restrict__ Btl,
            const float* __restrict__ Cin, float* __restrict__ D,
            __nv_bfloat16* __restrict__ Dh, __nv_bfloat16* __restrict__ Dl,
            int M, int N, int K) {
    extern __shared__ __nv_bfloat16 smp[];
    const int tid = threadIdx.x;
    const int wid = tid >> 5, lane = tid & 31;
    const int wm = wid & 3, wn = wid >> 2;
    const int m0 = blockIdx.y << 7, n0 = blockIdx.x << 7;
    const int gq = lane >> 2, kq = (lane & 3) << 1;

    uint32_t sbase;
    asm("{ .reg .u64 t; cvta.to.shared.u64 t, %1; cvt.u32.u64 %0, t; }"
        : "=r"(sbase) : "l"(smp));

    const int lr = tid >> 1;
    const int lc = (tid & 1) << 4;
    const __nv_bfloat16* gAh = Agh + (size_t)(m0 + lr) * K + lc;
    const __nv_bfloat16* gAl = Agl + (size_t)(m0 + lr) * K + lc;
    const __nv_bfloat16* gBh = Bth + (size_t)(n0 + lr) * K + lc;
    const __nv_bfloat16* gBl = Btl + (size_t)(n0 + lr) * K + lc;
    const uint32_t drow = (uint32_t)(lr * PITCH + lc) * 2;

    float acc[2][8][4];
#pragma unroll
    for (int mi = 0; mi < 2; mi++)
#pragma unroll
        for (int ni = 0; ni < 8; ni++)
#pragma unroll
            for (int j = 0; j < 4; j++) acc[mi][ni][j] = 0.f;

    const int nc = K >> 5;
    gemm_prefetch(sbase, 0, drow, K, gAh, gAl, gBh, gBl);
    CP_COMMIT();

    for (int c = 0; c < nc; c++) {
        if (c + 1 < nc) {
            gemm_prefetch(sbase, c + 1, drow, K, gAh, gAl, gBh, gBl);
            CP_COMMIT();
            CP_WAIT1();
        } else {
            CP_WAIT0();
        }
        __syncthreads();
        const __nv_bfloat16* sAh = smp + (c & 1) * (STG_B / 2);
        const __nv_bfloat16* sAl = sAh + ARR_B / 2;
        const __nv_bfloat16* sBh = sAh + ARR_B;
        const __nv_bfloat16* sBl = sAh + 3 * (ARR_B / 2);

#pragma unroll
        for (int ko = 0; ko < 32; ko += 16) {
            uint32_t bh[8][2], bl[8][2];
#pragma unroll
            for (int ni = 0; ni < 8; ni++) {
                int row = wn * 64 + ni * 8 + gq;
                bh[ni][0] = *(const uint32_t*)&sBh[row * PITCH + ko + kq];
                bh[ni][1] = *(const uint32_t*)&sBh[row * PITCH + ko + kq + 8];
                bl[ni][0] = *(const uint32_t*)&sBl[row * PITCH + ko + kq];
                bl[ni][1] = *(const uint32_t*)&sBl[row * PITCH + ko + kq + 8];
            }
#pragma unroll
            for (int mi = 0; mi < 2; mi++) {
                int r0 = wm * 32 + mi * 16 + gq;
                uint32_t ah[4], al[4];
                ah[0] = *(const uint32_t*)&sAh[r0 * PITCH + ko + kq];
                ah[1] = *(const uint32_t*)&sAh[(r0 + 8) * PITCH + ko + kq];
                ah[2] = *(const uint32_t*)&sAh[r0 * PITCH + ko + kq + 8];
                ah[3] = *(const uint32_t*)&sAh[(r0 + 8) * PITCH + ko + kq + 8];
                al[0] = *(const uint32_t*)&sAl[r0 * PITCH + ko + kq];
                al[1] = *(const uint32_t*)&sAl[(r0 + 8) * PITCH + ko + kq];
                al[2] = *(const uint32_t*)&sAl[r0 * PITCH + ko + kq + 8];
                al[3] = *(const uint32_t*)&sAl[(r0 + 8) * PITCH + ko + kq + 8];
#pragma unroll
                for (int ni = 0; ni < 8; ni++) {
                    mma16816(acc[mi][ni], ah, bh[ni]);
                    mma16816(acc[mi][ni], ah, bl[ni]);
                    mma16816(acc[mi][ni], al, bh[ni]);
                }
            }
        }
        __syncthreads();
    }

#pragma unroll
    for (int mi = 0; mi < 2; mi++) {
#pragma unroll
        for (int ni = 0; ni < 8; ni++) {
#pragma unroll
            for (int half = 0; half < 2; half++) {
                int r = m0 + wm * 32 + mi * 16 + gq + half * 8;
                int cc = n0 + wn * 64 + ni * 8 + kq;
                size_t o = (size_t)r * N + cc;
                float vx = acc[mi][ni][half * 2 + 0];
                float vy = acc[mi][ni][half * 2 + 1];
                if (EPI == 1) {
                    float2 ci = *(const float2*)(Cin + o);
                    *(float2*)(D + o) = make_float2(vx + ci.x, vy + ci.y);
                }
                if (EPI == 4) {
                    vx = 0.5f * vx * (1.f + erff(vx * 0.70710678118654752f));
                    vy = 0.5f * vy * (1.f + erff(vy * 0.70710678118654752f));
                }
                if (EPI == 3 || EPI == 4) {
                    uint32_t h, l;
                    split2(vx, vy, h, l);
                    *(uint32_t*)&Dh[o] = h;
                    *(uint32_t*)&Dl[o] = l;
                }
            }
        }
    }
}

// =========================================================================
// Tables: K-side cos/sin (bf16 hi/lo) and Q-side fp32 sin/cos, per position
// =========================================================================
__global__ void k_tab(__nv_bfloat16* __restrict__ tkh,
                      __nv_bfloat16* __restrict__ tkl,
                      float* __restrict__ scq) {
    int idx = blockIdx.x * blockDim.x + threadIdx.x;
    if (idx >= Tz * 32) return;
    int pos = idx >> 5, d = idx & 31;
    float f = expf(-logf(10000.f) * (2.f * (float)d) / 64.f);
    float ang = (float)pos * f;
    float s = sinf(ang), c = cosf(ang);
    // K-side: col d = cos, col 32+d = sin (bf16 hi/lo)
    __nv_bfloat16 ch = __float2bfloat16(c);
    tkh[pos * 64 + d] = ch;
    tkl[pos * 64 + d] = __float2bfloat16(c - __bfloat162float(ch));
    __nv_bfloat16 sh = __float2bfloat16(s);
    tkh[pos * 64 + 32 + d] = sh;
    tkl[pos * 64 + 32 + d] = __float2bfloat16(s - __bfloat162float(sh));
    // Q-side fp32: sin at d, cos at 32+d
    scq[pos * 64 + d] = s;
    scq[pos * 64 + 32 + d] = c;
}

// =========================================================================
// LayerNorm -> bf16 hi/lo
// =========================================================================
__global__ __launch_bounds__(256)
void k_ln(const float* __restrict__ x, const float* __restrict__ w,
          __nv_bfloat16* __restrict__ oh, __nv_bfloat16* __restrict__ ol) {
    __shared__ float red[256];
    int row = blockIdx.x;
    int tid = threadIdx.x;
    const float* xr = x + (size_t)row * Cz;
    float v0 = xr[tid], v1 = xr[tid + 256], v2 = xr[tid + 512];
    red[tid] = v0 + v1 + v2;
    __syncthreads();
    for (int o = 128; o > 0; o >>= 1) {
        if (tid < o) red[tid] += red[tid + o];
        __syncthreads();
    }
    float mean = red[0] * (1.f / Cz);
    __syncthreads();
    float d0 = v0 - mean, d1 = v1 - mean, d2 = v2 - mean;
    red[tid] = d0 * d0 + d1 * d1 + d2 * d2;
    __syncthreads();
    for (int o = 128; o > 0; o >>= 1) {
        if (tid < o) red[tid] += red[tid + o];
        __syncthreads();
    }
    float rstd = rsqrtf(red[0] * (1.f / Cz) + 1e-5f);
    size_t base = (size_t)row * Cz;
#pragma unroll
    for (int s = 0; s < 3; s++) {
        int cc = tid + s * 256;
        float v = ((s == 0) ? d0 : (s == 1) ? d1 : d2) * rstd * w[cc];
        __nv_bfloat16 h = __float2bfloat16(v);
        oh[base + cc] = h;
        ol[base + cc] = __float2bfloat16(v - __bfloat162float(h));
    }
}

// =========================================================================
// Tensor-core fused causal attention with SEPARABLE rel-pos.
// Q' = [q | u | v] (128 dims), K' = [k | cos(jf) | sin(jf)] (128 dims):
//   q.k + q.tab[i-j] == Q'.K'  exactly.  No qtab buffer, no gather.
// =========================================================================
#define APX 136

__global__ __launch_bounds__(128)
void k_attnm(const __nv_bfloat16* __restrict__ qkvh,
             const __nv_bfloat16* __restrict__ qkvl,
             const __nv_bfloat16* __restrict__ tkh,
             const __nv_bfloat16* __restrict__ tkl,
             const float* __restrict__ scq,
             __nv_bfloat16* __restrict__ yh, __nv_bfloat16* __restrict__ yl) {
    __shared__ __nv_bfloat16 sH[64 * APX], sL[64 * APX];

    int bh = blockIdx.x;
    int it = gridDim.y - 1 - blockIdx.y;
    int b = bh / Hz, h = bh % Hz;
    int i0 = it * 64;
    int tid = threadIdx.x;
    int wid = tid >> 5, lane = tid & 31;
    int gq = lane >> 2, kq = (lane & 3) << 1;
    int r = tid >> 1, half = tid & 1;

    // ---- Phase 1: load q (cols 0..63) ----
    {
        int cb = half << 5;
        const __nv_bfloat16* qh =
            qkvh + (size_t)(b * Tz + i0 + r) * (3 * Cz) + h * HDz + cb;
        const __nv_bfloat16* ql =
            qkvl + (size_t)(b * Tz + i0 + r) * (3 * Cz) + h * HDz + cb;
#pragma unroll
        for (int j = 0; j < 32; j += 8) {
            *(uint4*)&sH[r * APX + cb + j] = *(const uint4*)(qh + j);
            *(uint4*)&sL[r * APX + cb + j] = *(const uint4*)(ql + j);
        }
    }
    __syncthreads();
    // ---- Phase 2: build u (cols 64..95), v (cols 96..127) ----
    {
        const float* sc = scq + (size_t)(i0 + r) * 64;
#pragma unroll
        for (int dd = 0; dd < 16; dd++) {
            int d = (half << 4) + dd;
            float qd = __bfloat162float(sH[r * APX + d]) +
                       __bfloat162float(sL[r * APX + d]);
            float qd2 = __bfloat162float(sH[r * APX + 32 + d]) +
                        __bfloat162float(sL[r * APX + 32 + d]);
            float si = sc[d], ci = sc[32 + d];
            float u = qd * si + qd2 * ci;
            float v = qd2 * si - qd * ci;
            __nv_bfloat16 uh = __float2bfloat16(u);
            sH[r * APX + 64 + d] = uh;
            sL[r * APX + 64 + d] = __float2bfloat16(u - __bfloat162float(uh));
            __nv_bfloat16 vh = __float2bfloat16(v);
            sH[r * APX + 96 + d] = vh;
            sL[r * APX + 96 + d] = __float2bfloat16(v - __bfloat162float(vh));
        }
    }
    __syncthreads();

    // ---- Q' fragments in registers (8 k-steps over 128 dims) ----
    uint32_t aQh[8][4], aQl[8][4];
#pragma unroll
    for (int kt = 0; kt < 8; kt++) {
        int r0 = wid * 16 + gq, ko = kt * 16;
        aQh[kt][0] = *(const uint32_t*)&sH[r0 * APX + ko + kq];
        aQh[kt][1] = *(const uint32_t*)&sH[(r0 + 8) * APX + ko + kq];
        aQh[kt][2] = *(const uint32_t*)&sH[r0 * APX + ko + kq + 8];
        aQh[kt][3] = *(const uint32_t*)&sH[(r0 + 8) * APX + ko + kq + 8];
        aQl[kt][0] = *(const uint32_t*)&sL[r0 * APX + ko + kq];
        aQl[kt][1] = *(const uint32_t*)&sL[(r0 + 8) * APX + ko + kq];
        aQl[kt][2] = *(const uint32_t*)&sL[r0 * APX + ko + kq + 8];
        aQl[kt][3] = *(const uint32_t*)&sL[(r0 + 8) * APX + ko + kq + 8];
    }

    float O[8][4];
#pragma unroll
    for (int ni = 0; ni < 8; ni++)
#pragma unroll
        for (int j = 0; j < 4; j++) O[ni][j] = 0.f;
    float m_a = -1e30f, m_b = -1e30f, l_a = 0.f, l_b = 0.f;

    const int ia = i0 + wid * 16 + gq;
    const int ib = ia + 8;

    for (int jt = 0; jt <= it; jt++) {
        int j0 = jt * 64;
        __syncthreads();
        // ---- load K' tile: half 0 -> k data cols 0..63; half 1 -> table ----
        if (half == 0) {
            const __nv_bfloat16* kh =
                qkvh + (size_t)(b * Tz + j0 + r) * (3 * Cz) + Cz + h * HDz;
            const __nv_bfloat16* kl =
                qkvl + (size_t)(b * Tz + j0 + r) * (3 * Cz) + Cz + h * HDz;
#pragma unroll
            for (int j = 0; j < 64; j += 8) {
                *(uint4*)&sH[r * APX + j] = *(const uint4*)(kh + j);
                *(uint4*)&sL[r * APX + j] = *(const uint4*)(kl + j);
            }
        } else {
            const __nv_bfloat16* th = tkh + (size_t)(j0 + r) * 64;
            const __nv_bfloat16* tl = tkl + (size_t)(j0 + r) * 64;
#pragma unroll
            for (int j = 0; j < 64; j += 8) {
                *(uint4*)&sH[r * APX + 64 + j] = *(const uint4*)(th + j);
                *(uint4*)&sL[r * APX + 64 + j] = *(const uint4*)(tl + j);
            }
        }
        __syncthreads();

        // ---- scores over 128 dims ----
        float S[8][4];
#pragma unroll
        for (int ni = 0; ni < 8; ni++)
#pragma unroll
            for (int j = 0; j < 4; j++) S[ni][j] = 0.f;
#pragma unroll
        for (int kt = 0; kt < 8; kt++) {
            int ko = kt * 16;
#pragma unroll
            for (int ni = 0; ni < 8; ni++) {
                int row = ni * 8 + gq;
                uint32_t bh2[2], bl2[2];
                bh2[0] = *(const uint32_t*)&sH[row * APX + ko + kq];
                bh2[1] = *(const uint32_t*)&sH[row * APX + ko + kq + 8];
                bl2[0] = *(const uint32_t*)&sL[row * APX + ko + kq];
                bl2[1] = *(const uint32_t*)&sL[row * APX + ko + kq + 8];
                mma16816(S[ni], aQh[kt], bh2);
                mma16816(S[ni], aQh[kt], bl2);
                mma16816(S[ni], aQl[kt], bh2);
            }
        }

        // ---- causal mask (diag tile only) ----
        if (jt == it) {
#pragma unroll
            for (int ni = 0; ni < 8; ni++) {
                int jbase = j0 + ni * 8 + kq;
#pragma unroll
                for (int c = 0; c < 4; c++) {
                    int row = (c < 2) ? ia : ib;
                    int j = jbase + (c & 1);
                    if (j > row) S[ni][c] = -1e30f;
                }
            }
        }

        // ---- online softmax ----
        float mt_a = -1e30f, mt_b = -1e30f;
#pragma unroll
        for (int ni = 0; ni < 8; ni++) {
            mt_a = fmaxf(mt_a, fmaxf(S[ni][0], S[ni][1]));
            mt_b = fmaxf(mt_b, fmaxf(S[ni][2], S[ni][3]));
        }
        mt_a = fmaxf(mt_a, __shfl_xor_sync(0xffffffffu, mt_a, 1));
        mt_a = fmaxf(mt_a, __shfl_xor_sync(0xffffffffu, mt_a, 2));
        mt_b = fmaxf(mt_b, __shfl_xor_sync(0xffffffffu, mt_b, 1));
        mt_b = fmaxf(mt_b, __shfl_xor_sync(0xffffffffu, mt_b, 2));
        float mn_a = fmaxf(m_a, mt_a), mn_b = fmaxf(m_b, mt_b);
        float al_a = fexp2((m_a - mn_a) * CEXP);
        float al_b = fexp2((m_b - mn_b) * CEXP);
        m_a = mn_a;
        m_b = mn_b;
        float sum_a = 0.f, sum_b = 0.f;
#pragma unroll
        for (int ni = 0; ni < 8; ni++) {
            float p0 = fexp2((S[ni][0] - mn_a) * CEXP);
            float p1 = fexp2((S[ni][1] - mn_a) * CEXP);
            float p2 = fexp2((S[ni][2] - mn_b) * CEXP);
            float p3 = fexp2((S[ni][3] - mn_b) * CEXP);
            S[ni][0] = p0; S[ni][1] = p1; S[ni][2] = p2; S[ni][3] = p3;
            sum_a += p0 + p1;
            sum_b += p2 + p3;
        }
        sum_a += __shfl_xor_sync(0xffffffffu, sum_a, 1);
        sum_a += __shfl_xor_sync(0xffffffffu, sum_a, 2);
        sum_b += __shfl_xor_sync(0xffffffffu, sum_b, 1);
        sum_b += __shfl_xor_sync(0xffffffffu, sum_b, 2);
        l_a = l_a * al_a + sum_a;
        l_b = l_b * al_b + sum_b;
#pragma unroll
        for (int ni = 0; ni < 8; ni++) {
            O[ni][0] *= al_a;
            O[ni][1] *= al_a;
            O[ni][2] *= al_b;
            O[ni][3] *= al_b;
        }

        __syncthreads();
        // ---- load V tile transposed [d][j] into cols 0..63 ----
        {
            const size_t vbase =
                (size_t)(b * Tz + j0) * (3 * Cz) + 2 * Cz + h * HDz;
#pragma unroll
            for (int n = 0; n < 8; n++) {
                int u = n * 128 + tid;
                int j = (u >> 5) << 1;
                int d = (u & 31) << 1;
                const __nv_bfloat16* sh = qkvh + vbase + (size_t)j * (3 * Cz) + d;
                uint32_t va = *(const uint32_t*)sh;
                uint32_t vb = *(const uint32_t*)(sh + 3 * Cz);
                *(uint32_t*)&sH[d * APX + j] = __byte_perm(va, vb, 0x5410);
                *(uint32_t*)&sH[(d + 1) * APX + j] = __byte_perm(va, vb, 0x7632);
                const __nv_bfloat16* sl = qkvl + vbase + (size_t)j * (3 * Cz) + d;
                va = *(const uint32_t*)sl;
                vb = *(const uint32_t*)(sl + 3 * Cz);
                *(uint32_t*)&sL[d * APX + j] = __byte_perm(va, vb, 0x5410);
                *(uint32_t*)&sL[(d + 1) * APX + j] = __byte_perm(va, vb, 0x7632);
            }
        }
        __syncthreads();

        // ---- O += P @ V ----
#pragma unroll
        for (int kt = 0; kt < 4; kt++) {
            int ko = kt * 16;
            uint32_t aPh[4], aPl[4];
            split2(S[2 * kt][0], S[2 * kt][1], aPh[0], aPl[0]);
            split2(S[2 * kt][2], S[2 * kt][3], aPh[1], aPl[1]);
            split2(S[2 * kt + 1][0], S[2 * kt + 1][1], aPh[2], aPl[2]);
            split2(S[2 * kt + 1][2], S[2 * kt + 1][3], aPh[3], aPl[3]);
#pragma unroll
            for (int nd = 0; nd < 8; nd++) {
                int row = nd * 8 + gq;
                uint32_t bh2[2], bl2[2];
                bh2[0] = *(const uint32_t*)&sH[row * APX + ko + kq];
                bh2[1] = *(const uint32_t*)&sH[row * APX + ko + kq + 8];
                bl2[0] = *(const uint32_t*)&sL[row * APX + ko + kq];
                bl2[1] = *(const uint32_t*)&sL[row * APX + ko + kq + 8];
                mma16816(O[nd], aPh, bh2);
                mma16816(O[nd], aPh, bl2);
                mma16816(O[nd], aPl, bh2);
            }
        }
    }

    float inv_a = 1.f / l_a, inv_b = 1.f / l_b;
#pragma unroll
    for (int nd = 0; nd < 8; nd++) {
        int col = h * HDz + nd * 8 + kq;
        uint32_t h32, l32;
        split2(O[nd][0] * inv_a, O[nd][1] * inv_a, h32, l32);
        size_t oa = (size_t)(b * Tz + ia) * Cz + col;
        *(uint32_t*)&yh[oa] = h32;
        *(uint32_t*)&yl[oa] = l32;
        split2(O[nd][2] * inv_b, O[nd][3] * inv_b, h32, l32);
        size_t ob = (size_t)(b * Tz + ib) * Cz + col;
        *(uint32_t*)&yh[ob] = h32;
        *(uint32_t*)&yl[ob] = l32;
    }
}

// =========================================================================
// launcher (launch #4 = qkv GEMM, for the ncu capture window)
// =========================================================================
extern "C" void kernel_launch(void* const* d_in, const int* in_sizes, int n_in,
                              void* d_out, int out_size) {
    const float* x       = (const float*)d_in[0];
    const float* ln1_w   = (const float*)d_in[1];
    const float* w_attn  = (const float*)d_in[2];
    // d_in[3] = w_pos : dead code in the reference
    const float* w_cproj = (const float*)d_in[4];
    const float* ln2_w   = (const float*)d_in[5];
    const float* w_fc    = (const float*)d_in[6];
    const float* w_mproj = (const float*)d_in[7];
    float* out = (float*)d_out;

    float *scq, *x1;
    __nv_bfloat16 *bth, *btl, *qkvh, *qkvl, *tkh, *tkl;
    __nv_bfloat16 *hh, *hl, *yh, *yl, *h2h, *h2l, *fch, *fcl;
    cudaGetSymbolAddress((void**)&hh, g_hh);
    cudaGetSymbolAddress((void**)&hl, g_hl);
    cudaGetSymbolAddress((void**)&qkvh, g_qkvh);
    cudaGetSymbolAddress((void**)&qkvl, g_qkvl);
    cudaGetSymbolAddress((void**)&tkh, g_tkh);
    cudaGetSymbolAddress((void**)&tkl, g_tkl);
    cudaGetSymbolAddress((void**)&scq, g_scq);
    cudaGetSymbolAddress((void**)&yh, g_yh);
    cudaGetSymbolAddress((void**)&yl, g_yl);
    cudaGetSymbolAddress((void**)&x1, g_x1);
    cudaGetSymbolAddress((void**)&h2h, g_h2h);
    cudaGetSymbolAddress((void**)&h2l, g_h2l);
    cudaGetSymbolAddress((void**)&fch, g_fch);
    cudaGetSymbolAddress((void**)&fcl, g_fcl);
    cudaGetSymbolAddress((void**)&bth, g_bt_hi);
    cudaGetSymbolAddress((void**)&btl, g_bt_lo);

    cudaFuncSetAttribute(k_mma2<1>, cudaFuncAttributeMaxDynamicSharedMemorySize, SMEM_MMA);
    cudaFuncSetAttribute(k_mma2<3>, cudaFuncAttributeMaxDynamicSharedMemorySize, SMEM_MMA);
    cudaFuncSetAttribute(k_mma2<4>, cudaFuncAttributeMaxDynamicSharedMemorySize, SMEM_MMA);

    // 1. tables   2. LN1   3. attn-weight split   4. qkv GEMM (profiled)
    k_tab<<<(Tz * 32 + 255) / 256, 256>>>(tkh, tkl, scq);
    k_ln<<<BTz, 256>>>(x, ln1_w, hh, hl);
    k_tsplit<<<dim3(Cz / 32, (3 * Cz) / 32), 256>>>(w_attn, bth + WT_ATTN,
                                                    btl + WT_ATTN, Cz, 3 * Cz);
    k_mma2<3><<<dim3((3 * Cz) / 128, BTz / 128), 256, SMEM_MMA>>>(
        hh, hl, bth + WT_ATTN, btl + WT_ATTN, nullptr, nullptr, qkvh, qkvl,
        BTz, 3 * Cz, Cz);
    // 5. fused attention (rel-pos folded into QK')
    k_attnm<<<dim3(BHz, 16), 128>>>(qkvh, qkvl, tkh, tkl, scq, yh, yl);
    // 6-7. cproj
    k_tsplit<<<dim3(Cz / 32, Cz / 32), 256>>>(w_cproj, bth + WT_CPROJ,
                                              btl + WT_CPROJ, Cz, Cz);
    k_mma2<1><<<dim3(Cz / 128, BTz / 128), 256, SMEM_MMA>>>(
        yh, yl, bth + WT_CPROJ, btl + WT_CPROJ, x, x1, nullptr, nullptr,
        BTz, Cz, Cz);
    // 8. LN2
    k_ln<<<BTz, 256>>>(x1, ln2_w, h2h, h2l);
    // 9-10. fc + GELU
    k_tsplit<<<dim3(Cz / 32, (4 * Cz) / 32), 256>>>(w_fc, bth + WT_FC,
                                                    btl + WT_FC, Cz, 4 * Cz);
    k_mma2<4><<<dim3((4 * Cz) / 128, BTz / 128), 256, SMEM_MMA>>>(
        h2h, h2l, bth + WT_FC, btl + WT_FC, nullptr, nullptr, fch, fcl,
        BTz, 4 * Cz, Cz);
    // 11-12. mproj + residual
    k_tsplit<<<dim3((4 * Cz) / 32, Cz / 32), 256>>>(w_mproj, bth + WT_MPROJ,
                                                    btl + WT_MPROJ, 4 * Cz, Cz);
    k_mma2<1><<<dim3(Cz / 128, BTz / 128), 256, SMEM_MMA>>>(
        fch, fcl, bth + WT_MPROJ, btl + WT_MPROJ, x1, out, nullptr, nullptr,
        BTz, Cz, 4 * Cz);
}